// round 8
// baseline (speedup 1.0000x reference)
#include <cuda_runtime.h>

#define B_    8
#define N_    8192
#define M_    2048
#define C_    64
#define K_    32
#define CH_   67
#define ROWW  68
#define CELLS_ 1000
#define HMAX  256

// Scratch (device globals — no allocation allowed)
__device__ float  g_ptsT[B_ * N_ * ROWW];        // [b][n][68]
__device__ int    g_idx[B_ * M_ * K_];           // [b][m][32]
__device__ int    g_cellstart[B_ * (CELLS_ + 1)];
__device__ float4 g_pts4[B_ * N_];               // cell-sorted (x,y,z,idx-bits)

__device__ __forceinline__ int cell1d(float v) {
    int c = (int)(v * 10.0f);
    return c > 9 ? 9 : (c < 0 ? 0 : c);
}

// ---------------------------------------------------------------------------
// Kernel A: pack + transpose (B,3,N)+(B,64,N) -> ptsT[b][n][67(+1)]
// ---------------------------------------------------------------------------
__global__ void __launch_bounds__(256) transpose_k(const float* __restrict__ pc,
                                                   const float* __restrict__ feat) {
    __shared__ float tile[CH_][33];
    int b  = blockIdx.y;
    int n0 = blockIdx.x * 32;
    int tx = threadIdx.x;
    int ty = threadIdx.y;

    for (int ch = ty; ch < CH_; ch += 8) {
        float v = (ch < 3)
            ? pc[((size_t)(b * 3 + ch)) * N_ + n0 + tx]
            : feat[((size_t)(b * C_ + (ch - 3))) * N_ + n0 + tx];
        tile[ch][tx] = v;
    }
    __syncthreads();

    for (int r = ty; r < 32; r += 8) {
        float* row = g_ptsT + (size_t)(b * N_ + n0 + r) * ROWW;
        row[tx]      = tile[tx][r];
        row[32 + tx] = tile[32 + tx][r];
        if (tx < 3) row[64 + tx] = tile[64 + tx][r];
    }
}

// ---------------------------------------------------------------------------
// Fused grid build: one CTA per batch. count (smem atomics) -> two-level
// warp scan -> scatter to cell-sorted float4 array.
// ---------------------------------------------------------------------------
#define PPT (N_ / 1024)   // 8
__global__ void __launch_bounds__(1024) buildgrid_k(const float* __restrict__ pc) {
    __shared__ int scnt[CELLS_];
    __shared__ int scur[CELLS_];
    __shared__ int wsum[32];

    int b = blockIdx.x;
    int t = threadIdx.x;
    int lane = t & 31;
    int wid = t >> 5;

    for (int i = t; i < CELLS_; i += 1024) scnt[i] = 0;
    __syncthreads();

    const float* P = pc + (size_t)b * 3 * N_;
    float x[PPT], y[PPT], z[PPT];
    int cell[PPT];
    #pragma unroll
    for (int i = 0; i < PPT; i++) {
        int n = i * 1024 + t;
        x[i] = P[n]; y[i] = P[N_ + n]; z[i] = P[2 * N_ + n];
        cell[i] = (cell1d(x[i]) * 10 + cell1d(y[i])) * 10 + cell1d(z[i]);
        atomicAdd(&scnt[cell[i]], 1);
    }
    __syncthreads();

    int v = (t < CELLS_) ? scnt[t] : 0;
    int val = v;
    #pragma unroll
    for (int o = 1; o < 32; o <<= 1) {
        int u = __shfl_up_sync(0xffffffffu, v, o);
        if (lane >= o) v += u;
    }
    if (lane == 31) wsum[wid] = v;
    __syncthreads();
    if (wid == 0) {
        int w = wsum[lane];
        #pragma unroll
        for (int o = 1; o < 32; o <<= 1) {
            int u = __shfl_up_sync(0xffffffffu, w, o);
            if (lane >= o) w += u;
        }
        wsum[lane] = w;
    }
    __syncthreads();
    int incl = v + (wid > 0 ? wsum[wid - 1] : 0);
    int excl = incl - val;
    if (t < CELLS_) {
        g_cellstart[b * (CELLS_ + 1) + t] = excl;
        scur[t] = excl;
    }
    if (t == CELLS_ - 1) g_cellstart[b * (CELLS_ + 1) + CELLS_] = incl;
    __syncthreads();

    size_t bo = (size_t)b * N_;
    #pragma unroll
    for (int i = 0; i < PPT; i++) {
        int n = i * 1024 + t;
        int pos = atomicAdd(&scur[cell[i]], 1);
        g_pts4[bo + pos] = make_float4(x[i], y[i], z[i], __int_as_float(n));
    }
}

// ---------------------------------------------------------------------------
// Selection: 32 smallest indices from per-warp hit buffer (unordered).
// ---------------------------------------------------------------------------
template <int R>
__device__ __forceinline__ int select32(const int* __restrict__ hb, int cl,
                                        int cnt, int lane) {
    unsigned v[R];
    #pragma unroll
    for (int r = 0; r < R; r++) {
        int p = lane + 32 * r;
        v[r] = (p < cl) ? (unsigned)hb[p] : 0xffffffffu;
    }
    unsigned first = 0, kth = 0xffffffffu;
    #pragma unroll 1
    for (int it = 0; it < K_; it++) {
        unsigned lm = v[0];
        #pragma unroll
        for (int r = 1; r < R; r++) lm = min(lm, v[r]);
        unsigned mn = __reduce_min_sync(0xffffffffu, lm);
        if (mn == 0xffffffffu) break;
        if (it == 0) first = mn;
        if (it == lane) kth = mn;
        #pragma unroll
        for (int r = 0; r < R; r++) v[r] = (v[r] == mn) ? 0xffffffffu : v[r];
    }
    return (cnt == 0) ? 0 : ((lane < cnt) ? (int)kth : (int)first);
}

// ---------------------------------------------------------------------------
// Kernel B: grid ball query. One warp per center; 3x3x3 neighborhood via 9
// contiguous z-ranges. Exact hit test replicates reference numerics.
// ---------------------------------------------------------------------------
#define WARPS_Q 8
__global__ void __launch_bounds__(32 * WARPS_Q)
query_k(const float* __restrict__ cc) {
    __shared__ int hits[WARPS_Q][HMAX];
    int b    = blockIdx.y;
    int warp = threadIdx.x >> 5;
    int lane = threadIdx.x & 31;
    unsigned lmask_lt = (1u << lane) - 1u;
    int m = blockIdx.x * WARPS_Q + warp;
    int* hb = hits[warp];

    float cx = cc[(size_t)(b * 3 + 0) * M_ + m];
    float cy = cc[(size_t)(b * 3 + 1) * M_ + m];
    float cz = cc[(size_t)(b * 3 + 2) * M_ + m];
    float c2 = __fadd_rn(__fadd_rn(__fmul_rn(cx, cx), __fmul_rn(cy, cy)),
                         __fmul_rn(cz, cz));
    const float R2 = 0.01f;

    int icx = cell1d(cx), icy = cell1d(cy), icz = cell1d(cz);
    int zlo = icz > 0 ? icz - 1 : 0;
    int zhi = icz < 9 ? icz + 1 : 9;
    int xlo = icx > 0 ? icx - 1 : 0, xhi = icx < 9 ? icx + 1 : 9;
    int ylo = icy > 0 ? icy - 1 : 0, yhi = icy < 9 ? icy + 1 : 9;

    const int* cs = g_cellstart + b * (CELLS_ + 1);
    size_t bo = (size_t)b * N_;
    int cnt = 0;

    for (int dx = xlo; dx <= xhi; dx++) {
        for (int dy = ylo; dy <= yhi; dy++) {
            int base = (dx * 10 + dy) * 10;
            int s = cs[base + zlo];
            int e = cs[base + zhi + 1];
            for (int j0 = s; j0 < e; j0 += 32) {
                int j = j0 + lane;
                bool act = j < e;
                float4 p = g_pts4[bo + (act ? j : s)];
                float q = __fadd_rn(__fadd_rn(__fmul_rn(p.x, p.x), __fmul_rn(p.y, p.y)),
                                    __fmul_rn(p.z, p.z));
                float dot = __fmaf_rn(cz, p.z, __fmaf_rn(cy, p.y, __fmul_rn(cx, p.x)));
                float d2  = __fsub_rn(__fadd_rn(c2, q), __fadd_rn(dot, dot));
                bool hit = act && (d2 < R2);
                unsigned mask = __ballot_sync(0xffffffffu, hit);
                if (hit) {
                    int pos = cnt + __popc(mask & lmask_lt);
                    if (pos < HMAX) hb[pos] = __float_as_int(p.w);
                }
                cnt += __popc(mask);
            }
        }
    }
    __syncwarp();

    int cl = cnt > HMAX ? HMAX : cnt;
    int res;
    if (cl <= 32)       res = select32<1>(hb, cl, cnt, lane);
    else if (cl <= 64)  res = select32<2>(hb, cl, cnt, lane);
    else if (cl <= 128) res = select32<4>(hb, cl, cnt, lane);
    else                res = select32<8>(hb, cl, cnt, lane);

    g_idx[((size_t)b * M_ + m) * K_ + lane] = res;
}

// ---------------------------------------------------------------------------
// Kernel C: gather. TWO warps per center sharing one 67x33 tile:
//   half 0 loads neighbors 0..15, half 1 loads 16..31 (float4 row reads),
//   then half 0 writes channels [0,34), half 1 writes [34,67).
// 8 warps/CTA = 4 centers, 35.4KB smem -> 6 CTAs/SM (75% occ).
// ---------------------------------------------------------------------------
#define CPB_C 4   // centers per CTA
__global__ void __launch_bounds__(256)
gather_k(const float* __restrict__ cc, float* __restrict__ out) {
    extern __shared__ float smc[];   // CPB_C tiles of [CH_][33]
    int b    = blockIdx.y;
    int warp = threadIdx.x >> 5;
    int lane = threadIdx.x & 31;
    int pair = warp >> 1;            // 0..3  (center within CTA)
    int half = warp & 1;             // 0..1
    int m = blockIdx.x * CPB_C + pair;
    float* tile = smc + pair * (CH_ * 33);

    int my_i = g_idx[((size_t)b * M_ + m) * K_ + lane];

    // Each half-warp-pair loads 16 neighbor rows as float4 (272B rows, 16B aligned)
    #pragma unroll 4
    for (int jj = 0; jj < 16; jj++) {
        int j = half * 16 + jj;
        int ij = __shfl_sync(0xffffffffu, my_i, j);
        const float4* row4 = (const float4*)(g_ptsT + (size_t)(b * N_ + ij) * ROWW);
        if (lane < 17) {
            float4 v = row4[lane];
            int ch = lane * 4;
            tile[ch * 33 + j] = v.x;
            if (ch + 1 < CH_) tile[(ch + 1) * 33 + j] = v.y;
            if (ch + 2 < CH_) tile[(ch + 2) * 33 + j] = v.z;
            if (ch + 3 < CH_) tile[(ch + 3) * 33 + j] = v.w;
        }
    }
    __syncthreads();

    size_t obase = (((size_t)b * CH_) * M_ + m) * K_ + lane;
    const size_t cstride = (size_t)M_ * K_;

    if (half == 0) {
        float cx = cc[(size_t)(b * 3 + 0) * M_ + m];
        float cy = cc[(size_t)(b * 3 + 1) * M_ + m];
        float cz = cc[(size_t)(b * 3 + 2) * M_ + m];
        out[obase + 0 * cstride] = __fsub_rn(tile[0 * 33 + lane], cx);
        out[obase + 1 * cstride] = __fsub_rn(tile[1 * 33 + lane], cy);
        out[obase + 2 * cstride] = __fsub_rn(tile[2 * 33 + lane], cz);
        #pragma unroll
        for (int c = 3; c < 34; c++)
            out[obase + (size_t)c * cstride] = tile[c * 33 + lane];
    } else {
        #pragma unroll
        for (int c = 34; c < CH_; c++)
            out[obase + (size_t)c * cstride] = tile[c * 33 + lane];
    }
}

// ---------------------------------------------------------------------------
extern "C" void kernel_launch(void* const* d_in, const int* in_sizes, int n_in,
                              void* d_out, int out_size) {
    const float* points_coords  = (const float*)d_in[0];   // (8, 3, 8192)
    const float* centers_coords = (const float*)d_in[1];   // (8, 3, 2048)
    const float* points_feats   = (const float*)d_in[2];   // (8, 64, 8192)
    float* out = (float*)d_out;                            // (8, 67, 2048, 32)

    const int smem_g = CPB_C * CH_ * 33 * (int)sizeof(float);

    static bool init_done = false;
    static cudaStream_t s1;
    static cudaEvent_t e_fork, e_join;
    if (!init_done) {
        cudaFuncSetAttribute(gather_k, cudaFuncAttributeMaxDynamicSharedMemorySize, smem_g);
        cudaStreamCreateWithFlags(&s1, cudaStreamNonBlocking);
        cudaEventCreateWithFlags(&e_fork, cudaEventDisableTiming);
        cudaEventCreateWithFlags(&e_join, cudaEventDisableTiming);
        init_done = true;
    }

    cudaStream_t s0 = 0;

    // Fork: transpose on s1; grid build + query on s0 (independent)
    cudaEventRecord(e_fork, s0);
    cudaStreamWaitEvent(s1, e_fork, 0);

    {
        dim3 grid(N_ / 32, B_);
        dim3 block(32, 8);
        transpose_k<<<grid, block, 0, s1>>>(points_coords, points_feats);
    }

    buildgrid_k<<<B_, 1024, 0, s0>>>(points_coords);
    {
        dim3 grid(M_ / WARPS_Q, B_);
        query_k<<<grid, 32 * WARPS_Q, 0, s0>>>(centers_coords);
    }

    // Join: gather needs g_ptsT (s1) and g_idx (s0)
    cudaEventRecord(e_join, s1);
    cudaStreamWaitEvent(s0, e_join, 0);

    {
        dim3 grid(M_ / CPB_C, B_);
        gather_k<<<grid, 256, smem_g, s0>>>(centers_coords, out);
    }
}

// round 10
// speedup vs baseline: 1.1153x; 1.1153x over previous
#include <cuda_runtime.h>

#define B_    8
#define N_    8192
#define M_    2048
#define C_    64
#define K_    32
#define CH_   67
#define ROWW  68
#define CELLS_ 1000
#define HMAX  256

// Scratch (device globals — no allocation allowed)
__device__ float  g_ptsT[B_ * N_ * ROWW];        // [b][n][68]
__device__ int    g_idx[B_ * M_ * K_];           // [b][m][32]
__device__ int    g_cellstart[B_ * (CELLS_ + 1)];
__device__ float4 g_pts4[B_ * N_];               // cell-sorted (x,y,z,idx-bits)

__device__ __forceinline__ int cell1d(float v) {
    int c = (int)(v * 10.0f);
    return c > 9 ? 9 : (c < 0 ? 0 : c);
}

// ---------------------------------------------------------------------------
// Kernel A: pack + transpose (B,3,N)+(B,64,N) -> ptsT[b][n][67(+1)]
// ---------------------------------------------------------------------------
__global__ void __launch_bounds__(256) transpose_k(const float* __restrict__ pc,
                                                   const float* __restrict__ feat) {
    __shared__ float tile[CH_][33];
    int b  = blockIdx.y;
    int n0 = blockIdx.x * 32;
    int tx = threadIdx.x;
    int ty = threadIdx.y;

    for (int ch = ty; ch < CH_; ch += 8) {
        float v = (ch < 3)
            ? pc[((size_t)(b * 3 + ch)) * N_ + n0 + tx]
            : feat[((size_t)(b * C_ + (ch - 3))) * N_ + n0 + tx];
        tile[ch][tx] = v;
    }
    __syncthreads();

    for (int r = ty; r < 32; r += 8) {
        float* row = g_ptsT + (size_t)(b * N_ + n0 + r) * ROWW;
        row[tx]      = tile[tx][r];
        row[32 + tx] = tile[32 + tx][r];
        if (tx < 3) row[64 + tx] = tile[64 + tx][r];
    }
}

// ---------------------------------------------------------------------------
// Fused grid build: one CTA per batch. count (smem atomics) -> two-level
// warp scan -> scatter to cell-sorted float4 array.
// ---------------------------------------------------------------------------
#define PPT (N_ / 1024)   // 8
__global__ void __launch_bounds__(1024) buildgrid_k(const float* __restrict__ pc) {
    __shared__ int scnt[CELLS_];
    __shared__ int scur[CELLS_];
    __shared__ int wsum[32];

    int b = blockIdx.x;
    int t = threadIdx.x;
    int lane = t & 31;
    int wid = t >> 5;

    for (int i = t; i < CELLS_; i += 1024) scnt[i] = 0;
    __syncthreads();

    const float* P = pc + (size_t)b * 3 * N_;
    float x[PPT], y[PPT], z[PPT];
    int cell[PPT];
    #pragma unroll
    for (int i = 0; i < PPT; i++) {
        int n = i * 1024 + t;
        x[i] = P[n]; y[i] = P[N_ + n]; z[i] = P[2 * N_ + n];
        cell[i] = (cell1d(x[i]) * 10 + cell1d(y[i])) * 10 + cell1d(z[i]);
        atomicAdd(&scnt[cell[i]], 1);
    }
    __syncthreads();

    int v = (t < CELLS_) ? scnt[t] : 0;
    int val = v;
    #pragma unroll
    for (int o = 1; o < 32; o <<= 1) {
        int u = __shfl_up_sync(0xffffffffu, v, o);
        if (lane >= o) v += u;
    }
    if (lane == 31) wsum[wid] = v;
    __syncthreads();
    if (wid == 0) {
        int w = wsum[lane];
        #pragma unroll
        for (int o = 1; o < 32; o <<= 1) {
            int u = __shfl_up_sync(0xffffffffu, w, o);
            if (lane >= o) w += u;
        }
        wsum[lane] = w;
    }
    __syncthreads();
    int incl = v + (wid > 0 ? wsum[wid - 1] : 0);
    int excl = incl - val;
    if (t < CELLS_) {
        g_cellstart[b * (CELLS_ + 1) + t] = excl;
        scur[t] = excl;
    }
    if (t == CELLS_ - 1) g_cellstart[b * (CELLS_ + 1) + CELLS_] = incl;
    __syncthreads();

    size_t bo = (size_t)b * N_;
    #pragma unroll
    for (int i = 0; i < PPT; i++) {
        int n = i * 1024 + t;
        int pos = atomicAdd(&scur[cell[i]], 1);
        g_pts4[bo + pos] = make_float4(x[i], y[i], z[i], __int_as_float(n));
    }
}

// ---------------------------------------------------------------------------
// Selection: 32 smallest indices from per-warp hit buffer (unordered).
// ---------------------------------------------------------------------------
template <int R>
__device__ __forceinline__ int select32(const int* __restrict__ hb, int cl,
                                        int cnt, int lane) {
    unsigned v[R];
    #pragma unroll
    for (int r = 0; r < R; r++) {
        int p = lane + 32 * r;
        v[r] = (p < cl) ? (unsigned)hb[p] : 0xffffffffu;
    }
    unsigned first = 0, kth = 0xffffffffu;
    #pragma unroll 1
    for (int it = 0; it < K_; it++) {
        unsigned lm = v[0];
        #pragma unroll
        for (int r = 1; r < R; r++) lm = min(lm, v[r]);
        unsigned mn = __reduce_min_sync(0xffffffffu, lm);
        if (mn == 0xffffffffu) break;
        if (it == 0) first = mn;
        if (it == lane) kth = mn;
        #pragma unroll
        for (int r = 0; r < R; r++) v[r] = (v[r] == mn) ? 0xffffffffu : v[r];
    }
    return (cnt == 0) ? 0 : ((lane < cnt) ? (int)kth : (int)first);
}

// ---------------------------------------------------------------------------
// Kernel B: grid ball query. One warp per center; 3x3x3 neighborhood via 9
// contiguous z-ranges. Exact hit test replicates reference numerics.
// ---------------------------------------------------------------------------
#define WARPS_Q 8
__global__ void __launch_bounds__(32 * WARPS_Q)
query_k(const float* __restrict__ cc) {
    __shared__ int hits[WARPS_Q][HMAX];
    int b    = blockIdx.y;
    int warp = threadIdx.x >> 5;
    int lane = threadIdx.x & 31;
    unsigned lmask_lt = (1u << lane) - 1u;
    int m = blockIdx.x * WARPS_Q + warp;
    int* hb = hits[warp];

    float cx = cc[(size_t)(b * 3 + 0) * M_ + m];
    float cy = cc[(size_t)(b * 3 + 1) * M_ + m];
    float cz = cc[(size_t)(b * 3 + 2) * M_ + m];
    float c2 = __fadd_rn(__fadd_rn(__fmul_rn(cx, cx), __fmul_rn(cy, cy)),
                         __fmul_rn(cz, cz));
    const float R2 = 0.01f;

    int icx = cell1d(cx), icy = cell1d(cy), icz = cell1d(cz);
    int zlo = icz > 0 ? icz - 1 : 0;
    int zhi = icz < 9 ? icz + 1 : 9;
    int xlo = icx > 0 ? icx - 1 : 0, xhi = icx < 9 ? icx + 1 : 9;
    int ylo = icy > 0 ? icy - 1 : 0, yhi = icy < 9 ? icy + 1 : 9;

    const int* cs = g_cellstart + b * (CELLS_ + 1);
    size_t bo = (size_t)b * N_;
    int cnt = 0;

    for (int dx = xlo; dx <= xhi; dx++) {
        for (int dy = ylo; dy <= yhi; dy++) {
            int base = (dx * 10 + dy) * 10;
            int s = cs[base + zlo];
            int e = cs[base + zhi + 1];
            for (int j0 = s; j0 < e; j0 += 32) {
                int j = j0 + lane;
                bool act = j < e;
                float4 p = g_pts4[bo + (act ? j : s)];
                float q = __fadd_rn(__fadd_rn(__fmul_rn(p.x, p.x), __fmul_rn(p.y, p.y)),
                                    __fmul_rn(p.z, p.z));
                float dot = __fmaf_rn(cz, p.z, __fmaf_rn(cy, p.y, __fmul_rn(cx, p.x)));
                float d2  = __fsub_rn(__fadd_rn(c2, q), __fadd_rn(dot, dot));
                bool hit = act && (d2 < R2);
                unsigned mask = __ballot_sync(0xffffffffu, hit);
                if (hit) {
                    int pos = cnt + __popc(mask & lmask_lt);
                    if (pos < HMAX) hb[pos] = __float_as_int(p.w);
                }
                cnt += __popc(mask);
            }
        }
    }
    __syncwarp();

    int cl = cnt > HMAX ? HMAX : cnt;
    int res;
    if (cl <= 32)       res = select32<1>(hb, cl, cnt, lane);
    else if (cl <= 64)  res = select32<2>(hb, cl, cnt, lane);
    else if (cl <= 128) res = select32<4>(hb, cl, cnt, lane);
    else                res = select32<8>(hb, cl, cnt, lane);

    g_idx[((size_t)b * M_ + m) * K_ + lane] = res;
}

// ---------------------------------------------------------------------------
// Kernel C: gather. One warp per center, TWO channel passes over a half-size
// tile (35x33 = 4.6KB/warp -> 8 warps/CTA, 37KB/CTA, 6 CTAs/SM = 75% occ).
// Access pattern identical to the fast R6 version: full-warp coalesced LDG
// per neighbor, conflict-free stride-33 STS, coalesced 128B STG.
// ---------------------------------------------------------------------------
#define WARPS_C 8
#define TILE_W 33
#define TILE_ROWS 35
__global__ void __launch_bounds__(32 * WARPS_C)
gather_k(const float* __restrict__ cc, float* __restrict__ out) {
    extern __shared__ float smc[];   // WARPS_C tiles of [35][33]
    int b    = blockIdx.y;
    int warp = threadIdx.x >> 5;
    int lane = threadIdx.x & 31;
    int m = blockIdx.x * WARPS_C + warp;
    float* tile = smc + warp * (TILE_ROWS * TILE_W);

    int my_i = g_idx[((size_t)b * M_ + m) * K_ + lane];

    size_t obase = (((size_t)b * CH_) * M_ + m) * K_ + lane;
    const size_t cstride = (size_t)M_ * K_;

    // ---- Pass A: channels [0, 32) ----
    #pragma unroll 4
    for (int j = 0; j < K_; j++) {
        int ij = __shfl_sync(0xffffffffu, my_i, j);
        const float* row = g_ptsT + (size_t)(b * N_ + ij) * ROWW;
        tile[lane * TILE_W + j] = row[lane];
    }
    __syncwarp();

    float cx = cc[(size_t)(b * 3 + 0) * M_ + m];
    float cy = cc[(size_t)(b * 3 + 1) * M_ + m];
    float cz = cc[(size_t)(b * 3 + 2) * M_ + m];
    out[obase + 0 * cstride] = __fsub_rn(tile[0 * TILE_W + lane], cx);
    out[obase + 1 * cstride] = __fsub_rn(tile[1 * TILE_W + lane], cy);
    out[obase + 2 * cstride] = __fsub_rn(tile[2 * TILE_W + lane], cz);
    #pragma unroll
    for (int c = 3; c < 32; c++)
        out[obase + (size_t)c * cstride] = tile[c * TILE_W + lane];
    __syncwarp();

    // ---- Pass B: channels [32, 67) ----
    #pragma unroll 4
    for (int j = 0; j < K_; j++) {
        int ij = __shfl_sync(0xffffffffu, my_i, j);
        const float* row = g_ptsT + (size_t)(b * N_ + ij) * ROWW;
        tile[lane * TILE_W + j] = row[32 + lane];
        if (lane < 3) tile[(32 + lane) * TILE_W + j] = row[64 + lane];
    }
    __syncwarp();

    #pragma unroll
    for (int c = 0; c < TILE_ROWS; c++)
        out[obase + (size_t)(32 + c) * cstride] = tile[c * TILE_W + lane];
}

// ---------------------------------------------------------------------------
extern "C" void kernel_launch(void* const* d_in, const int* in_sizes, int n_in,
                              void* d_out, int out_size) {
    const float* points_coords  = (const float*)d_in[0];   // (8, 3, 8192)
    const float* centers_coords = (const float*)d_in[1];   // (8, 3, 2048)
    const float* points_feats   = (const float*)d_in[2];   // (8, 64, 8192)
    float* out = (float*)d_out;                            // (8, 67, 2048, 32)

    const int smem_g = WARPS_C * TILE_ROWS * TILE_W * (int)sizeof(float);

    static bool init_done = false;
    static cudaStream_t s1;
    static cudaEvent_t e_fork, e_join;
    if (!init_done) {
        cudaFuncSetAttribute(gather_k, cudaFuncAttributeMaxDynamicSharedMemorySize, smem_g);
        cudaStreamCreateWithFlags(&s1, cudaStreamNonBlocking);
        cudaEventCreateWithFlags(&e_fork, cudaEventDisableTiming);
        cudaEventCreateWithFlags(&e_join, cudaEventDisableTiming);
        init_done = true;
    }

    cudaStream_t s0 = 0;

    // Fork: transpose on s1; grid build + query on s0 (independent)
    cudaEventRecord(e_fork, s0);
    cudaStreamWaitEvent(s1, e_fork, 0);

    {
        dim3 grid(N_ / 32, B_);
        dim3 block(32, 8);
        transpose_k<<<grid, block, 0, s1>>>(points_coords, points_feats);
    }

    buildgrid_k<<<B_, 1024, 0, s0>>>(points_coords);
    {
        dim3 grid(M_ / WARPS_Q, B_);
        query_k<<<grid, 32 * WARPS_Q, 0, s0>>>(centers_coords);
    }

    // Join: gather needs g_ptsT (s1) and g_idx (s0)
    cudaEventRecord(e_join, s1);
    cudaStreamWaitEvent(s0, e_join, 0);

    {
        dim3 grid(M_ / WARPS_C, B_);
        gather_k<<<grid, 32 * WARPS_C, smem_g, s0>>>(centers_coords, out);
    }
}